// round 15
// baseline (speedup 1.0000x reference)
#include <cuda_runtime.h>

#define BATCH 8
#define DIM 256
#define SEQ 16384
#define KK 3
#define HID 85
#define OUTC (DIM*KK)
#define BN_EPS 1e-5f
#define FULLM 0xffffffffu

#define NCTA 512
#define NTHR 512
#define RPC 4                     // rows per CTA (4 consecutive, same batch)

// Device globals (no allocation allowed). Barrier is gen-based and
// self-resetting -> safe across graph replays.
__device__ float g_pooled[BATCH * DIM];
__device__ unsigned g_cnt2 = 0;
__device__ unsigned g_gen2 = 0;

__global__ void __launch_bounds__(NTHR, 4)
fused2_kernel(const float* __restrict__ x,
              const float* __restrict__ w1,
              const float* __restrict__ gamma,
              const float* __restrict__ beta,
              const float* __restrict__ mean,
              const float* __restrict__ var,
              const float* __restrict__ w2,
              const float* __restrict__ b2,
              const float* __restrict__ bias,
              float* __restrict__ out) {
    const int cta = blockIdx.x;            // 0..511
    const int tid = threadIdx.x;
    const int lane = tid & 31;
    const int row0 = cta * RPC;            // global row = b*DIM + c
    const int b = row0 >> 8;
    const int c0 = row0 & 255;

    __shared__ float sm4[16][RPC];
    __shared__ float ps[DIM];
    __shared__ float ys[HID];
    __shared__ float wloc[RPC * KK];
    __shared__ float bl[RPC];

    // ================= Phase 1: pool own 4 rows (streaming) ===============
    float s[RPC];
    #pragma unroll
    for (int r = 0; r < RPC; r++) {
        const float4* rp = (const float4*)(x + (size_t)(row0 + r) * SEQ);
        float4 v[8];
        #pragma unroll
        for (int j = 0; j < 8; j++)
            v[j] = rp[tid + j * NTHR];
        float acc = 0.f;
        #pragma unroll
        for (int j = 0; j < 8; j++)
            acc += (v[j].x + v[j].y) + (v[j].z + v[j].w);
        s[r] = acc;
    }
    #pragma unroll
    for (int r = 0; r < RPC; r++) {
        #pragma unroll
        for (int off = 16; off > 0; off >>= 1)
            s[r] += __shfl_down_sync(FULLM, s[r], off);
    }
    if (lane == 0) {
        #pragma unroll
        for (int r = 0; r < RPC; r++) sm4[tid >> 5][r] = s[r];
    }
    __syncthreads();
    if (tid < RPC) {
        float t = 0.f;
        #pragma unroll
        for (int w = 0; w < 16; w++) t += sm4[w][tid];
        g_pooled[row0 + tid] = t * (1.f / SEQ);
    }

    // ================= Grid barrier (gen-based, self-resetting) ===========
    __syncthreads();
    if (tid == 0) {
        unsigned gen = *(volatile unsigned*)&g_gen2;
        __threadfence();                           // publish g_pooled
        unsigned my = atomicAdd(&g_cnt2, 1u);
        if (my == NCTA - 1) {
            g_cnt2 = 0;
            __threadfence();
            atomicAdd(&g_gen2, 1u);
        } else {
            while (*(volatile unsigned*)&g_gen2 == gen) __nanosleep(64);
        }
        __threadfence();                           // acquire
    }
    __syncthreads();

    // ================= Phase 2: redundant per-CTA MLP =====================
    if (tid < DIM) ps[tid] = __ldcg(g_pooled + b * DIM + tid);
    __syncthreads();
    if (tid < HID) {
        const float* wr = w1 + tid * DIM;
        float acc = 0.f;
        #pragma unroll 8
        for (int k = 0; k < DIM; k++) acc = fmaf(__ldg(wr + k), ps[k], acc);
        float y = (acc - mean[tid]) * (gamma[tid] * rsqrtf(var[tid] + BN_EPS)) + beta[tid];
        ys[tid] = fmaxf(y, 0.f);
    }
    __syncthreads();
    if (tid < RPC * KK) {                          // 12 taps for our 4 rows
        const int o = c0 * KK + tid;               // FIXED: within-batch index into w2/b2
        const float* wr = w2 + o * HID;
        float acc = b2[o];
        #pragma unroll 5
        for (int h = 0; h < HID; h++) acc = fmaf(__ldg(wr + h), ys[h], acc);
        wloc[tid] = acc;
    }
    if (tid >= 32 && tid < 32 + RPC) bl[tid - 32] = __ldg(bias + c0 + (tid - 32));
    __syncthreads();

    // ================= Phase 3: conv own 4 rows (L2-hot) ==================
    #pragma unroll
    for (int r = 0; r < RPC; r++) {
        const size_t rowoff = (size_t)(row0 + r) * SEQ;
        const float w0  = wloc[r * KK + 0];
        const float w1v = wloc[r * KK + 1];
        const float w2v = wloc[r * KK + 2];
        const float bb  = bl[r];

        #pragma unroll
        for (int g = 0; g < 2; g++) {
            int t[4];
            float4 v[4];
            #pragma unroll
            for (int j = 0; j < 4; j++) {
                t[j] = ((g * 4 + j) * NTHR + tid) * 4;
                v[j] = *(const float4*)(x + rowoff + t[j]);
            }
            #pragma unroll
            for (int j = 0; j < 4; j++) {
                float xl = __shfl_up_sync(FULLM, v[j].w, 1);
                float xr = __shfl_down_sync(FULLM, v[j].x, 1);
                if (lane == 0)
                    xl = (t[j] == 0) ? 0.f : __ldg(x + rowoff + t[j] - 1);
                if (lane == 31)
                    xr = (t[j] + 4 >= SEQ) ? 0.f : __ldg(x + rowoff + t[j] + 4);

                float4 o;
                o.x = fmaf(w0, xl,     fmaf(w1v, v[j].x, fmaf(w2v, v[j].y, bb)));
                o.y = fmaf(w0, v[j].x, fmaf(w1v, v[j].y, fmaf(w2v, v[j].z, bb)));
                o.z = fmaf(w0, v[j].y, fmaf(w1v, v[j].z, fmaf(w2v, v[j].w, bb)));
                o.w = fmaf(w0, v[j].z, fmaf(w1v, v[j].w, fmaf(w2v, xr,     bb)));

                __stcs((float4*)(out + rowoff + t[j]), o);
            }
        }
    }
}

// ---------------------------------------------------------------------------
// Launch. Inputs (metadata order): x, w1, bn_gamma, bn_beta, bn_mean, bn_var,
// w2, b2, bias. Output: fp32 [8, 256, 16384].
// ---------------------------------------------------------------------------
extern "C" void kernel_launch(void* const* d_in, const int* in_sizes, int n_in,
                              void* d_out, int out_size) {
    const float* x     = (const float*)d_in[0];
    const float* w1    = (const float*)d_in[1];
    const float* gamma = (const float*)d_in[2];
    const float* beta  = (const float*)d_in[3];
    const float* mean  = (const float*)d_in[4];
    const float* var   = (const float*)d_in[5];
    const float* w2    = (const float*)d_in[6];
    const float* b2    = (const float*)d_in[7];
    const float* bias  = (const float*)d_in[8];
    float* out = (float*)d_out;

    fused2_kernel<<<NCTA, NTHR>>>(x, w1, gamma, beta, mean, var,
                                  w2, b2, bias, out);
}

// round 16
// speedup vs baseline: 1.1511x; 1.1511x over previous
#include <cuda_runtime.h>

#define BATCH 8
#define DIM 256
#define SEQ 16384
#define KK 3
#define HID 85
#define OUTC (DIM*KK)
#define BN_EPS 1e-5f
#define FULLM 0xffffffffu

#define NCTA 444                  // 148 SMs x 3 -> co-resident (152-SM GB300 too)
#define NTHR 512
#define NROWMAX 5                 // 2048 = 272*5 + 172*4

// Device globals (no allocation). Barrier is generation-based and
// self-resetting -> safe across graph replays (gen strictly increases).
__device__ float g_pooled[BATCH * DIM];
__device__ float g_w[BATCH * OUTC];
__device__ unsigned g_bcnt = 0;
__device__ unsigned g_bgen = 0;

__device__ __forceinline__ void grid_barrier_512() {
    __syncthreads();
    if (threadIdx.x == 0) {
        unsigned gen = *(volatile unsigned*)&g_bgen;
        __threadfence();
        unsigned my = atomicAdd(&g_bcnt, 1u);
        if (my == NCTA - 1) {
            g_bcnt = 0;
            __threadfence();
            atomicAdd(&g_bgen, 1u);
        } else {
            while (*(volatile unsigned*)&g_bgen == gen) __nanosleep(64);
        }
        __threadfence();
    }
    __syncthreads();
}

__global__ void __launch_bounds__(NTHR, 3)
fused3_kernel(const float* __restrict__ x,
              const float* __restrict__ w1,
              const float* __restrict__ gamma,
              const float* __restrict__ beta,
              const float* __restrict__ mean,
              const float* __restrict__ var,
              const float* __restrict__ w2,
              const float* __restrict__ b2,
              const float* __restrict__ bias,
              float* __restrict__ out) {
    const int cta = blockIdx.x;            // 0..443
    const int tid = threadIdx.x;
    const int lane = tid & 31;
    const int wid = tid >> 5;              // 0..15
    const int nr = (cta < 272) ? 5 : 4;    // owned rows: cta + 444*j

    __shared__ float smW[16][NROWMAX];
    __shared__ float ps[DIM];
    __shared__ float ys[HID];

    // ================= Phase 1: pool owned rows (2x4 front-batched f4) ====
    float s[NROWMAX];
    #pragma unroll
    for (int r = 0; r < NROWMAX; r++) {
        if (r >= nr) break;
        const int row = cta + r * NCTA;
        const float4* rp = (const float4*)(x + (size_t)row * SEQ);
        float acc = 0.f;
        #pragma unroll
        for (int g = 0; g < 2; g++) {
            float4 v[4];
            #pragma unroll
            for (int j = 0; j < 4; j++)
                v[j] = rp[g * 2048 + j * NTHR + tid];
            #pragma unroll
            for (int j = 0; j < 4; j++)
                acc += (v[j].x + v[j].y) + (v[j].z + v[j].w);
        }
        s[r] = acc;
    }
    #pragma unroll
    for (int r = 0; r < NROWMAX; r++) {
        if (r >= nr) break;
        #pragma unroll
        for (int off = 16; off > 0; off >>= 1)
            s[r] += __shfl_down_sync(FULLM, s[r], off);
        if (lane == 0) smW[wid][r] = s[r];
    }
    __syncthreads();
    if (tid < nr) {
        float t = 0.f;
        #pragma unroll
        for (int w = 0; w < 16; w++) t += smW[w][tid];
        g_pooled[cta + tid * NCTA] = t * (1.f / SEQ);
    }

    // ================= Barrier 1: pooled complete =========================
    grid_barrier_512();

    // ================= Phase 2: CTAs 0..7 compute the per-batch MLP =======
    if (cta < BATCH) {
        const int b = cta;
        if (tid < DIM) ps[tid] = __ldcg(g_pooled + b * DIM + tid);
        __syncthreads();
        if (tid < HID) {
            const float* wr = w1 + tid * DIM;
            float acc = 0.f;
            #pragma unroll 8
            for (int k = 0; k < DIM; k++) acc = fmaf(__ldg(wr + k), ps[k], acc);
            float y = (acc - mean[tid]) * (gamma[tid] * rsqrtf(var[tid] + BN_EPS)) + beta[tid];
            ys[tid] = fmaxf(y, 0.f);
        }
        __syncthreads();
        #pragma unroll
        for (int rep = 0; rep < 2; rep++) {
            const int o = rep * NTHR + tid;
            if (o < OUTC) {
                const float* wr = w2 + o * HID;
                float acc = b2[o];
                #pragma unroll 5
                for (int h = 0; h < HID; h++) acc = fmaf(__ldg(wr + h), ys[h], acc);
                g_w[b * OUTC + o] = acc;
            }
        }
    }

    // ================= Barrier 2: g_w complete ============================
    grid_barrier_512();

    // ================= Phase 3: conv owned rows, NEWEST-FIRST =============
    // (reverse row order + reverse group order -> consume the most recently
    //  loaded, still-L2-resident x lines before the store stream evicts them)
    #pragma unroll 1
    for (int r = nr - 1; r >= 0; r--) {
        const int row = cta + r * NCTA;                  // row = b*DIM + c
        const size_t rowoff = (size_t)row * SEQ;
        const float w0  = __ldcg(g_w + 3 * row + 0);     // b*OUTC + c*3 == 3*row
        const float w1v = __ldcg(g_w + 3 * row + 1);
        const float w2v = __ldcg(g_w + 3 * row + 2);
        const float bb  = __ldg(bias + (row & 255));

        #pragma unroll
        for (int g = 1; g >= 0; g--) {
            int t[4];
            float4 v[4];
            #pragma unroll
            for (int j = 0; j < 4; j++) {
                t[j] = (g * 2048 + j * NTHR + tid) * 4;
                v[j] = *(const float4*)(x + rowoff + t[j]);
            }
            #pragma unroll
            for (int j = 0; j < 4; j++) {
                float xl = __shfl_up_sync(FULLM, v[j].w, 1);
                float xr = __shfl_down_sync(FULLM, v[j].x, 1);
                if (lane == 0)
                    xl = (t[j] == 0) ? 0.f : __ldg(x + rowoff + t[j] - 1);
                if (lane == 31)
                    xr = (t[j] + 4 >= SEQ) ? 0.f : __ldg(x + rowoff + t[j] + 4);

                float4 o;
                o.x = fmaf(w0, xl,     fmaf(w1v, v[j].x, fmaf(w2v, v[j].y, bb)));
                o.y = fmaf(w0, v[j].x, fmaf(w1v, v[j].y, fmaf(w2v, v[j].z, bb)));
                o.z = fmaf(w0, v[j].y, fmaf(w1v, v[j].z, fmaf(w2v, v[j].w, bb)));
                o.w = fmaf(w0, v[j].z, fmaf(w1v, v[j].w, fmaf(w2v, xr,     bb)));

                __stcs((float4*)(out + rowoff + t[j]), o);
            }
        }
    }
}

// ---------------------------------------------------------------------------
// Launch. Inputs (metadata order): x, w1, bn_gamma, bn_beta, bn_mean, bn_var,
// w2, b2, bias. Output: fp32 [8, 256, 16384].
// ---------------------------------------------------------------------------
extern "C" void kernel_launch(void* const* d_in, const int* in_sizes, int n_in,
                              void* d_out, int out_size) {
    const float* x     = (const float*)d_in[0];
    const float* w1    = (const float*)d_in[1];
    const float* gamma = (const float*)d_in[2];
    const float* beta  = (const float*)d_in[3];
    const float* mean  = (const float*)d_in[4];
    const float* var   = (const float*)d_in[5];
    const float* w2    = (const float*)d_in[6];
    const float* b2    = (const float*)d_in[7];
    const float* bias  = (const float*)d_in[8];
    float* out = (float*)d_out;

    fused3_kernel<<<NCTA, NTHR>>>(x, w1, gamma, beta, mean, var,
                                  w2, b2, bias, out);
}